// round 2
// baseline (speedup 1.0000x reference)
#include <cuda_runtime.h>
#include <math.h>

#define T_SEQ   4096
#define C_DIM   1024
#define NHEADS  16
#define HDIM    64

// ---------------- scratch (static device globals; no allocation) -------------
__device__ float g_normed[T_SEQ * C_DIM];
__device__ float g_q[T_SEQ * C_DIM];
__device__ float g_k[T_SEQ * C_DIM];
__device__ float g_v[T_SEQ * C_DIM];
__device__ float g_att[T_SEQ * C_DIM];

// ---------------- RMSNorm ----------------------------------------------------
__global__ void rmsnorm_kernel(const float* __restrict__ x,
                               const float* __restrict__ w,
                               float* __restrict__ out)
{
    int row = blockIdx.x;
    const float4* xr = reinterpret_cast<const float4*>(x + (size_t)row * C_DIM);
    float ss = 0.f;
    for (int i = threadIdx.x; i < C_DIM / 4; i += blockDim.x) {
        float4 v = xr[i];
        ss += v.x * v.x + v.y * v.y + v.z * v.z + v.w * v.w;
    }
#pragma unroll
    for (int o = 16; o; o >>= 1) ss += __shfl_xor_sync(0xffffffffu, ss, o);

    __shared__ float red[8];
    __shared__ float s_inv;
    if ((threadIdx.x & 31) == 0) red[threadIdx.x >> 5] = ss;
    __syncthreads();
    if (threadIdx.x == 0) {
        float tot = 0.f;
        int nw = blockDim.x >> 5;
        for (int i = 0; i < nw; i++) tot += red[i];
        s_inv = rsqrtf(tot * (1.0f / C_DIM) + 1e-6f);
    }
    __syncthreads();
    float inv = s_inv;
    const float4* wr = reinterpret_cast<const float4*>(w);
    float4* outr = reinterpret_cast<float4*>(out + (size_t)row * C_DIM);
    for (int i = threadIdx.x; i < C_DIM / 4; i += blockDim.x) {
        float4 v = xr[i], ww = wr[i];
        v.x = v.x * inv * ww.x;
        v.y = v.y * inv * ww.y;
        v.z = v.z * inv * ww.z;
        v.w = v.w * inv * ww.w;
        outr[i] = v;
    }
}

// ---------------- SGEMM: C[M,N] = A[M,K] * B[N,K]^T (+Res) -------------------
#define BM 128
#define BN 128
#define BK 8

__global__ __launch_bounds__(256, 2)
void sgemm_nt_kernel(const float* __restrict__ A, const float* __restrict__ B,
                     const float* __restrict__ Res, float* __restrict__ Cm,
                     int M, int N, int K)
{
    __shared__ float As[BK][BM];
    __shared__ float Bs[BK][BN];

    int tid = threadIdx.x;
    int lr = tid >> 1;
    int lc = (tid & 1) * 4;
    const float* Ag = A + (size_t)(blockIdx.y * BM + lr) * K + lc;
    const float* Bg = B + (size_t)(blockIdx.x * BN + lr) * K + lc;
    int tx = tid & 15, ty = tid >> 4;

    float acc[8][8];
#pragma unroll
    for (int i = 0; i < 8; i++)
#pragma unroll
        for (int j = 0; j < 8; j++) acc[i][j] = 0.f;

    for (int k0 = 0; k0 < K; k0 += BK) {
        float4 a = *reinterpret_cast<const float4*>(Ag + k0);
        float4 b = *reinterpret_cast<const float4*>(Bg + k0);
        As[lc + 0][lr] = a.x; As[lc + 1][lr] = a.y;
        As[lc + 2][lr] = a.z; As[lc + 3][lr] = a.w;
        Bs[lc + 0][lr] = b.x; Bs[lc + 1][lr] = b.y;
        Bs[lc + 2][lr] = b.z; Bs[lc + 3][lr] = b.w;
        __syncthreads();
#pragma unroll
        for (int k = 0; k < BK; k++) {
            float4 a0 = *reinterpret_cast<const float4*>(&As[k][ty * 8]);
            float4 a1 = *reinterpret_cast<const float4*>(&As[k][ty * 8 + 4]);
            float4 b0 = *reinterpret_cast<const float4*>(&Bs[k][tx * 8]);
            float4 b1 = *reinterpret_cast<const float4*>(&Bs[k][tx * 8 + 4]);
            float ar[8] = {a0.x, a0.y, a0.z, a0.w, a1.x, a1.y, a1.z, a1.w};
            float br[8] = {b0.x, b0.y, b0.z, b0.w, b1.x, b1.y, b1.z, b1.w};
#pragma unroll
            for (int i = 0; i < 8; i++)
#pragma unroll
                for (int j = 0; j < 8; j++)
                    acc[i][j] += ar[i] * br[j];
        }
        __syncthreads();
    }

#pragma unroll
    for (int i = 0; i < 8; i++) {
        int row = blockIdx.y * BM + ty * 8 + i;
        float* crow = Cm + (size_t)row * N + blockIdx.x * BN + tx * 8;
        if (Res) {
            const float* rrow = Res + (size_t)row * N + blockIdx.x * BN + tx * 8;
#pragma unroll
            for (int j = 0; j < 8; j++) acc[i][j] += rrow[j];
        }
        *reinterpret_cast<float4*>(crow) =
            make_float4(acc[i][0], acc[i][1], acc[i][2], acc[i][3]);
        *reinterpret_cast<float4*>(crow + 4) =
            make_float4(acc[i][4], acc[i][5], acc[i][6], acc[i][7]);
    }
}

// ---------------- RoPE (applied to q and k in place) -------------------------
__global__ void rope_kernel(float* __restrict__ q, float* __restrict__ k)
{
    int idx = blockIdx.x * blockDim.x + threadIdx.x;
    if (idx >= T_SEQ * NHEADS * 32) return;
    int i = idx & 31;
    int h = (idx >> 5) & (NHEADS - 1);
    int t = idx >> 9;
    float freq = powf(10000.0f, -(float)(2 * i) * (1.0f / 64.0f));
    float f = (float)t * freq;
    float s, c;
    sincosf(f, &s, &c);
    int base = t * C_DIM + h * HDIM;
    float q1 = q[base + i], q2 = q[base + i + 32];
    q[base + i]      = q1 * c - q2 * s;
    q[base + i + 32] = q2 * c + q1 * s;
    float k1 = k[base + i], k2 = k[base + i + 32];
    k[base + i]      = k1 * c - k2 * s;
    k[base + i + 32] = k2 * c + k1 * s;
}

// ---------------- Flash attention (causal, fp32, online softmax) -------------
#define FS 68   // smem row stride (floats): 16B-aligned rows, conflict-spread
#define FLASH_SMEM (4 * 64 * FS * 4)

__global__ __launch_bounds__(256)
void flash_kernel(const float* __restrict__ Qg, const float* __restrict__ Kg,
                  const float* __restrict__ Vg, float* __restrict__ Og)
{
    extern __shared__ float sm[];
    float* Qs = sm;              // [64][FS]  Qs[r][d]
    float* Ks = Qs + 64 * FS;    // [64][FS]  transposed: Ks[d][n]
    float* Vs = Ks + 64 * FS;    // [64][FS]  Vs[c][d]
    float* Ps = Vs + 64 * FS;    // [64][FS]  Ps[r][c]

    int qt = (gridDim.x - 1) - blockIdx.x;  // heavy tiles first
    int h  = blockIdx.y;
    int tid = threadIdx.x;
    int tx = tid & 15, ty = tid >> 4;
    int r0 = ty * 4, c0 = tx * 4;

    int lrow = tid >> 2;        // 0..63
    int lq   = tid & 3;         // quarter of a 64-float row

    // load Q tile [64 rows x 64 dh]
    {
        const float* src = Qg + (size_t)(qt * 64 + lrow) * C_DIM + h * HDIM + lq * 16;
        float* dst = Qs + lrow * FS + lq * 16;
#pragma unroll
        for (int v = 0; v < 4; v++)
            *reinterpret_cast<float4*>(dst + v * 4) =
                *reinterpret_cast<const float4*>(src + v * 4);
    }

    float o[4][4];
    float m[4], l[4];
#pragma unroll
    for (int i = 0; i < 4; i++) {
        m[i] = -INFINITY; l[i] = 0.f;
#pragma unroll
        for (int j = 0; j < 4; j++) o[i][j] = 0.f;
    }

    for (int j = 0; j <= qt; j++) {
        __syncthreads();  // prior tile's reads of Ks/Vs/Ps complete (also Q vis. on iter 0)
        // load K transposed + V
        {
            const float* ksrc = Kg + (size_t)(j * 64 + lrow) * C_DIM + h * HDIM + lq * 16;
#pragma unroll
            for (int v = 0; v < 4; v++) {
                float4 kv = *reinterpret_cast<const float4*>(ksrc + v * 4);
                int cb = lq * 16 + v * 4;
                Ks[(cb + 0) * FS + lrow] = kv.x;
                Ks[(cb + 1) * FS + lrow] = kv.y;
                Ks[(cb + 2) * FS + lrow] = kv.z;
                Ks[(cb + 3) * FS + lrow] = kv.w;
            }
            const float* vsrc = Vg + (size_t)(j * 64 + lrow) * C_DIM + h * HDIM + lq * 16;
            float* vdst = Vs + lrow * FS + lq * 16;
#pragma unroll
            for (int v = 0; v < 4; v++)
                *reinterpret_cast<float4*>(vdst + v * 4) =
                    *reinterpret_cast<const float4*>(vsrc + v * 4);
        }
        __syncthreads();

        // S = Q K^T  (4x4 microtile)
        float s[4][4];
#pragma unroll
        for (int i = 0; i < 4; i++)
#pragma unroll
            for (int jj = 0; jj < 4; jj++) s[i][jj] = 0.f;

        for (int k = 0; k < 64; k++) {
            float4 b = *reinterpret_cast<const float4*>(&Ks[k * FS + c0]);
#pragma unroll
            for (int i = 0; i < 4; i++) {
                float a = Qs[(r0 + i) * FS + k];
                s[i][0] += a * b.x; s[i][1] += a * b.y;
                s[i][2] += a * b.z; s[i][3] += a * b.w;
            }
        }

        // scale + causal mask (diagonal tile only)
        const float sc = 0.125f;  // 1/sqrt(64)
        if (j == qt) {
#pragma unroll
            for (int i = 0; i < 4; i++)
#pragma unroll
                for (int jj = 0; jj < 4; jj++) {
                    int rr = r0 + i, cc = c0 + jj;
                    s[i][jj] = (cc <= rr) ? s[i][jj] * sc : -INFINITY;
                }
        } else {
#pragma unroll
            for (int i = 0; i < 4; i++)
#pragma unroll
                for (int jj = 0; jj < 4; jj++) s[i][jj] *= sc;
        }

        // online softmax
        float alpha[4];
#pragma unroll
        for (int i = 0; i < 4; i++) {
            float rm = fmaxf(fmaxf(s[i][0], s[i][1]), fmaxf(s[i][2], s[i][3]));
#pragma unroll
            for (int off = 1; off < 16; off <<= 1)
                rm = fmaxf(rm, __shfl_xor_sync(0xffffffffu, rm, off, 16));
            float mnew = fmaxf(m[i], rm);
            alpha[i] = __expf(m[i] - mnew);
            m[i] = mnew;
            float rs = 0.f;
#pragma unroll
            for (int jj = 0; jj < 4; jj++) {
                float p = __expf(s[i][jj] - mnew);
                s[i][jj] = p;
                rs += p;
            }
#pragma unroll
            for (int off = 1; off < 16; off <<= 1)
                rs += __shfl_xor_sync(0xffffffffu, rs, off, 16);
            l[i] = l[i] * alpha[i] + rs;
            *reinterpret_cast<float4*>(&Ps[(r0 + i) * FS + c0]) =
                make_float4(s[i][0], s[i][1], s[i][2], s[i][3]);
        }
        __syncthreads();  // Ps visible to all

        // O = O*alpha + P V
#pragma unroll
        for (int i = 0; i < 4; i++)
#pragma unroll
            for (int jj = 0; jj < 4; jj++) o[i][jj] *= alpha[i];

        for (int c = 0; c < 64; c++) {
            float4 v4 = *reinterpret_cast<const float4*>(&Vs[c * FS + c0]);
#pragma unroll
            for (int i = 0; i < 4; i++) {
                float p = Ps[(r0 + i) * FS + c];
                o[i][0] += p * v4.x; o[i][1] += p * v4.y;
                o[i][2] += p * v4.z; o[i][3] += p * v4.w;
            }
        }
    }

    // epilogue: normalize + store
#pragma unroll
    for (int i = 0; i < 4; i++) {
        float invl = 1.f / l[i];
        float* dst = Og + (size_t)(qt * 64 + r0 + i) * C_DIM + h * HDIM + c0;
        *reinterpret_cast<float4*>(dst) =
            make_float4(o[i][0] * invl, o[i][1] * invl, o[i][2] * invl, o[i][3] * invl);
    }
}

// ---------------- launch -----------------------------------------------------
extern "C" void kernel_launch(void* const* d_in, const int* in_sizes, int n_in,
                              void* d_out, int out_size)
{
    const float* x      = (const float*)d_in[0];
    const float* wq     = (const float*)d_in[1];
    const float* wk     = (const float*)d_in[2];
    const float* wv     = (const float*)d_in[3];
    const float* wo     = (const float*)d_in[4];
    const float* norm_w = (const float*)d_in[5];
    float* out = (float*)d_out;

    float *normed, *q, *k, *v, *att;
    cudaGetSymbolAddress((void**)&normed, g_normed);
    cudaGetSymbolAddress((void**)&q,      g_q);
    cudaGetSymbolAddress((void**)&k,      g_k);
    cudaGetSymbolAddress((void**)&v,      g_v);
    cudaGetSymbolAddress((void**)&att,    g_att);

    // 1) RMSNorm
    rmsnorm_kernel<<<T_SEQ, 256>>>(x, norm_w, normed);

    // 2) Q/K/V projections: [4096,1024] @ W^T
    dim3 gdim(C_DIM / BN, T_SEQ / BM);
    sgemm_nt_kernel<<<gdim, 256>>>(normed, wq, nullptr, q, T_SEQ, C_DIM, C_DIM);
    sgemm_nt_kernel<<<gdim, 256>>>(normed, wk, nullptr, k, T_SEQ, C_DIM, C_DIM);
    sgemm_nt_kernel<<<gdim, 256>>>(normed, wv, nullptr, v, T_SEQ, C_DIM, C_DIM);

    // 3) RoPE on q,k
    int nrope = T_SEQ * NHEADS * 32;
    rope_kernel<<<(nrope + 255) / 256, 256>>>(q, k);

    // 4) causal flash attention
    cudaFuncSetAttribute(flash_kernel, cudaFuncAttributeMaxDynamicSharedMemorySize,
                         FLASH_SMEM);
    dim3 fgrid(T_SEQ / 64, NHEADS);
    flash_kernel<<<fgrid, 256, FLASH_SMEM>>>(q, k, v, att);

    // 5) output projection + residual
    sgemm_nt_kernel<<<gdim, 256>>>(att, wo, x, out, T_SEQ, C_DIM, C_DIM);
}

// round 4
// speedup vs baseline: 1.1447x; 1.1447x over previous
#include <cuda_runtime.h>
#include <math.h>
#include <stdint.h>

#define T_SEQ   4096
#define C_DIM   1024
#define NHEADS  16
#define HDIM    64

// ---------------- scratch (static device globals; no allocation) -------------
__device__ float g_normed[T_SEQ * C_DIM];
__device__ float g_q[T_SEQ * C_DIM];
__device__ float g_k[T_SEQ * C_DIM];
__device__ float g_v[T_SEQ * C_DIM];
__device__ float g_att[T_SEQ * C_DIM];

// ================= tf32 split helpers ========================================
__device__ __forceinline__ void split_tf32(float a, float& hi, float& lo)
{
    uint32_t h;
    asm("cvt.rna.tf32.f32 %0, %1;" : "=r"(h) : "f"(a));
    hi = __uint_as_float(h);
    float r = a - hi;
    uint32_t l2;
    asm("cvt.rna.tf32.f32 %0, %1;" : "=r"(l2) : "f"(r));
    lo = __uint_as_float(l2);
}

// m16n8k8 tf32 mma (sm_80+ baseline PTX, runs on tensor pipe)
__device__ __forceinline__ void mma_tf32(float d[4],
                                         float a0, float a1, float a2, float a3,
                                         float b0, float b1)
{
    asm volatile(
        "mma.sync.aligned.m16n8k8.row.col.f32.tf32.tf32.f32 "
        "{%0,%1,%2,%3}, {%4,%5,%6,%7}, {%8,%9}, {%0,%1,%2,%3};"
        : "+f"(d[0]), "+f"(d[1]), "+f"(d[2]), "+f"(d[3])
        : "r"(__float_as_uint(a0)), "r"(__float_as_uint(a1)),
          "r"(__float_as_uint(a2)), "r"(__float_as_uint(a3)),
          "r"(__float_as_uint(b0)), "r"(__float_as_uint(b1)));
}

// ================= HMMA tf32 GEMM: C[M,N] = A[M,K] @ B[N,K]^T (+Res) =========
// 128x128 CTA tile, BK=32, 8 warps (2m x 4n), each warp 64x32.
// 3-term tf32 split: hi*hi + lo*hi + hi*lo.
#define G_BM 128
#define G_BN 128
#define G_BK 32
#define G_SK 36                          // padded k-stride (floats)
#define G_PLANE (128 * G_SK)             // 4608 floats per plane
#define G_BUF   (4 * G_PLANE)            // Ahi, Alo, Bhi, Blo
#define G_SMEM_TOTAL (2 * G_BUF * 4)     // bytes = 147456

__device__ __forceinline__ void ldg_tile(const float* __restrict__ G, int ldk,
                                         int k0, int tid, float4 r[4])
{
#pragma unroll
    for (int v = 0; v < 4; v++) {
        int i = tid + v * 256;
        int row = i >> 3;
        int c4 = i & 7;
        r[v] = *reinterpret_cast<const float4*>(G + (size_t)row * ldk + k0 + c4 * 4);
    }
}

__device__ __forceinline__ void sts_split(const float4 r[4], float* __restrict__ hi,
                                          float* __restrict__ lo, int tid)
{
#pragma unroll
    for (int v = 0; v < 4; v++) {
        int i = tid + v * 256;
        int row = i >> 3;
        int c4 = i & 7;
        int off = row * G_SK + c4 * 4;
        float4 h4, l4;
        split_tf32(r[v].x, h4.x, l4.x);
        split_tf32(r[v].y, h4.y, l4.y);
        split_tf32(r[v].z, h4.z, l4.z);
        split_tf32(r[v].w, h4.w, l4.w);
        *reinterpret_cast<float4*>(hi + off) = h4;
        *reinterpret_cast<float4*>(lo + off) = l4;
    }
}

__global__ __launch_bounds__(256, 1)
void gemm_mma_kernel(const float* __restrict__ A, const float* __restrict__ B,
                     const float* __restrict__ Res, float* __restrict__ Cm,
                     int M, int N, int K)
{
    extern __shared__ float sm[];
    int tid = threadIdx.x;
    int wid = tid >> 5;
    int lane = tid & 31;
    int gid = lane >> 2;    // 0..7  (row group)
    int tig = lane & 3;     // 0..3  (thread in group)
    int wm = wid & 1;       // 2 m-slabs of 64
    int wn = wid >> 1;      // 4 n-slabs of 32

    const float* Atile = A + (size_t)(blockIdx.y * G_BM) * K;
    const float* Btile = B + (size_t)(blockIdx.x * G_BN) * K;

    float acc[4][4][4];
#pragma unroll
    for (int mi = 0; mi < 4; mi++)
#pragma unroll
        for (int ni = 0; ni < 4; ni++)
#pragma unroll
            for (int e = 0; e < 4; e++) acc[mi][ni][e] = 0.f;

    const int NCHUNK = K / G_BK;   // 32

    // prologue: chunk 0 -> buf 0
    float4 ra[4], rb[4];
    ldg_tile(Atile, K, 0, tid, ra);
    ldg_tile(Btile, K, 0, tid, rb);
    {
        float* base = sm;
        sts_split(ra, base + 0 * G_PLANE, base + 1 * G_PLANE, tid);
        sts_split(rb, base + 2 * G_PLANE, base + 3 * G_PLANE, tid);
    }
    __syncthreads();

    for (int kc = 0; kc < NCHUNK; kc++) {
        int cur = kc & 1;
        // prefetch next chunk into registers (latency hidden under compute)
        if (kc + 1 < NCHUNK) {
            ldg_tile(Atile, K, (kc + 1) * G_BK, tid, ra);
            ldg_tile(Btile, K, (kc + 1) * G_BK, tid, rb);
        }

        const float* Ahi = sm + cur * G_BUF;
        const float* Alo = Ahi + G_PLANE;
        const float* Bhi = Alo + G_PLANE;
        const float* Blo = Bhi + G_PLANE;

#pragma unroll
        for (int ks = 0; ks < 4; ks++) {
            int kk = ks * 8;
            float Ah[4][4], Al[4][4];
#pragma unroll
            for (int mi = 0; mi < 4; mi++) {
                int mrow = wm * 64 + mi * 16 + gid;
                int base = mrow * G_SK + kk + tig;
                Ah[mi][0] = Ahi[base];
                Ah[mi][1] = Ahi[base + 8 * G_SK];
                Ah[mi][2] = Ahi[base + 4];
                Ah[mi][3] = Ahi[base + 8 * G_SK + 4];
                Al[mi][0] = Alo[base];
                Al[mi][1] = Alo[base + 8 * G_SK];
                Al[mi][2] = Alo[base + 4];
                Al[mi][3] = Alo[base + 8 * G_SK + 4];
            }
            float Bh[4][2], Bl[4][2];
#pragma unroll
            for (int ni = 0; ni < 4; ni++) {
                int ncol = wn * 32 + ni * 8 + gid;
                int base = ncol * G_SK + kk + tig;
                Bh[ni][0] = Bhi[base];
                Bh[ni][1] = Bhi[base + 4];
                Bl[ni][0] = Blo[base];
                Bl[ni][1] = Blo[base + 4];
            }
#pragma unroll
            for (int mi = 0; mi < 4; mi++)
#pragma unroll
                for (int ni = 0; ni < 4; ni++) {
                    mma_tf32(acc[mi][ni], Ah[mi][0], Ah[mi][1], Ah[mi][2], Ah[mi][3],
                             Bh[ni][0], Bh[ni][1]);
                    mma_tf32(acc[mi][ni], Al[mi][0], Al[mi][1], Al[mi][2], Al[mi][3],
                             Bh[ni][0], Bh[ni][1]);
                    mma_tf32(acc[mi][ni], Ah[mi][0], Ah[mi][1], Ah[mi][2], Ah[mi][3],
                             Bl[ni][0], Bl[ni][1]);
                }
        }

        // stage next chunk into the other buffer
        if (kc + 1 < NCHUNK) {
            float* base = sm + (1 - cur) * G_BUF;
            sts_split(ra, base + 0 * G_PLANE, base + 1 * G_PLANE, tid);
            sts_split(rb, base + 2 * G_PLANE, base + 3 * G_PLANE, tid);
        }
        __syncthreads();
    }

    // epilogue
#pragma unroll
    for (int mi = 0; mi < 4; mi++) {
        int row0 = blockIdx.y * G_BM + wm * 64 + mi * 16 + gid;
#pragma unroll
        for (int ni = 0; ni < 4; ni++) {
            int col = blockIdx.x * G_BN + wn * 32 + ni * 8 + 2 * tig;
            float* d0 = Cm + (size_t)row0 * N + col;
            float* d1 = Cm + (size_t)(row0 + 8) * N + col;
            float2 v0 = make_float2(acc[mi][ni][0], acc[mi][ni][1]);
            float2 v1 = make_float2(acc[mi][ni][2], acc[mi][ni][3]);
            if (Res) {
                const float2 r0 = *reinterpret_cast<const float2*>(Res + (size_t)row0 * N + col);
                const float2 r1 = *reinterpret_cast<const float2*>(Res + (size_t)(row0 + 8) * N + col);
                v0.x += r0.x; v0.y += r0.y;
                v1.x += r1.x; v1.y += r1.y;
            }
            *reinterpret_cast<float2*>(d0) = v0;
            *reinterpret_cast<float2*>(d1) = v1;
        }
    }
}

// ---------------- RMSNorm ----------------------------------------------------
__global__ void rmsnorm_kernel(const float* __restrict__ x,
                               const float* __restrict__ w,
                               float* __restrict__ out)
{
    int row = blockIdx.x;
    const float4* xr = reinterpret_cast<const float4*>(x + (size_t)row * C_DIM);
    float ss = 0.f;
    for (int i = threadIdx.x; i < C_DIM / 4; i += blockDim.x) {
        float4 v = xr[i];
        ss += v.x * v.x + v.y * v.y + v.z * v.z + v.w * v.w;
    }
#pragma unroll
    for (int o = 16; o; o >>= 1) ss += __shfl_xor_sync(0xffffffffu, ss, o);

    __shared__ float red[8];
    __shared__ float s_inv;
    if ((threadIdx.x & 31) == 0) red[threadIdx.x >> 5] = ss;
    __syncthreads();
    if (threadIdx.x == 0) {
        float tot = 0.f;
        int nw = blockDim.x >> 5;
        for (int i = 0; i < nw; i++) tot += red[i];
        s_inv = rsqrtf(tot * (1.0f / C_DIM) + 1e-6f);
    }
    __syncthreads();
    float inv = s_inv;
    const float4* wr = reinterpret_cast<const float4*>(w);
    float4* outr = reinterpret_cast<float4*>(out + (size_t)row * C_DIM);
    for (int i = threadIdx.x; i < C_DIM / 4; i += blockDim.x) {
        float4 v = xr[i], ww = wr[i];
        v.x = v.x * inv * ww.x;
        v.y = v.y * inv * ww.y;
        v.z = v.z * inv * ww.z;
        v.w = v.w * inv * ww.w;
        outr[i] = v;
    }
}

// ---------------- RoPE (applied to q and k in place) -------------------------
__global__ void rope_kernel(float* __restrict__ q, float* __restrict__ k)
{
    int idx = blockIdx.x * blockDim.x + threadIdx.x;
    if (idx >= T_SEQ * NHEADS * 32) return;
    int i = idx & 31;
    int h = (idx >> 5) & (NHEADS - 1);
    int t = idx >> 9;
    float freq = powf(10000.0f, -(float)(2 * i) * (1.0f / 64.0f));
    float f = (float)t * freq;
    float s, c;
    sincosf(f, &s, &c);
    int base = t * C_DIM + h * HDIM;
    float q1 = q[base + i], q2 = q[base + i + 32];
    q[base + i]      = q1 * c - q2 * s;
    q[base + i + 32] = q2 * c + q1 * s;
    float k1 = k[base + i], k2 = k[base + i + 32];
    k[base + i]      = k1 * c - k2 * s;
    k[base + i + 32] = k2 * c + k1 * s;
}

// ---------------- Flash attention (causal, fp32, online softmax) -------------
#define FS 68   // smem row stride (floats): 16B-aligned rows, conflict-spread
#define FLASH_SMEM (4 * 64 * FS * 4)

__global__ __launch_bounds__(256)
void flash_kernel(const float* __restrict__ Qg, const float* __restrict__ Kg,
                  const float* __restrict__ Vg, float* __restrict__ Og)
{
    extern __shared__ float sm[];
    float* Qs = sm;              // [64][FS]  Qs[r][d]
    float* Ks = Qs + 64 * FS;    // [64][FS]  transposed: Ks[d][n]
    float* Vs = Ks + 64 * FS;    // [64][FS]  Vs[c][d]
    float* Ps = Vs + 64 * FS;    // [64][FS]  Ps[r][c]

    int qt = (gridDim.x - 1) - blockIdx.x;  // heavy tiles first
    int h  = blockIdx.y;
    int tid = threadIdx.x;
    int tx = tid & 15, ty = tid >> 4;
    int r0 = ty * 4, c0 = tx * 4;

    int lrow = tid >> 2;        // 0..63
    int lq   = tid & 3;         // quarter of a 64-float row

    // load Q tile [64 rows x 64 dh]
    {
        const float* src = Qg + (size_t)(qt * 64 + lrow) * C_DIM + h * HDIM + lq * 16;
        float* dst = Qs + lrow * FS + lq * 16;
#pragma unroll
        for (int v = 0; v < 4; v++)
            *reinterpret_cast<float4*>(dst + v * 4) =
                *reinterpret_cast<const float4*>(src + v * 4);
    }

    float o[4][4];
    float m[4], l[4];
#pragma unroll
    for (int i = 0; i < 4; i++) {
        m[i] = -INFINITY; l[i] = 0.f;
#pragma unroll
        for (int j = 0; j < 4; j++) o[i][j] = 0.f;
    }

    for (int j = 0; j <= qt; j++) {
        __syncthreads();  // prior tile's reads of Ks/Vs/Ps complete (also Q vis. on iter 0)
        // load K transposed + V
        {
            const float* ksrc = Kg + (size_t)(j * 64 + lrow) * C_DIM + h * HDIM + lq * 16;
#pragma unroll
            for (int v = 0; v < 4; v++) {
                float4 kv = *reinterpret_cast<const float4*>(ksrc + v * 4);
                int cb = lq * 16 + v * 4;
                Ks[(cb + 0) * FS + lrow] = kv.x;
                Ks[(cb + 1) * FS + lrow] = kv.y;
                Ks[(cb + 2) * FS + lrow] = kv.z;
                Ks[(cb + 3) * FS + lrow] = kv.w;
            }
            const float* vsrc = Vg + (size_t)(j * 64 + lrow) * C_DIM + h * HDIM + lq * 16;
            float* vdst = Vs + lrow * FS + lq * 16;
#pragma unroll
            for (int v = 0; v < 4; v++)
                *reinterpret_cast<float4*>(vdst + v * 4) =
                    *reinterpret_cast<const float4*>(vsrc + v * 4);
        }
        __syncthreads();

        // S = Q K^T  (4x4 microtile)
        float s[4][4];
#pragma unroll
        for (int i = 0; i < 4; i++)
#pragma unroll
            for (int jj = 0; jj < 4; jj++) s[i][jj] = 0.f;

        for (int k = 0; k < 64; k++) {
            float4 b = *reinterpret_cast<const float4*>(&Ks[k * FS + c0]);
#pragma unroll
            for (int i = 0; i < 4; i++) {
                float a = Qs[(r0 + i) * FS + k];
                s[i][0] += a * b.x; s[i][1] += a * b.y;
                s[i][2] += a * b.z; s[i][3] += a * b.w;
            }
        }

        // scale + causal mask (diagonal tile only)
        const float sc = 0.125f;  // 1/sqrt(64)
        if (j == qt) {
#pragma unroll
            for (int i = 0; i < 4; i++)
#pragma unroll
                for (int jj = 0; jj < 4; jj++) {
                    int rr = r0 + i, cc = c0 + jj;
                    s[i][jj] = (cc <= rr) ? s[i][jj] * sc : -INFINITY;
                }
        } else {
#pragma unroll
            for (int i = 0; i < 4; i++)
#pragma unroll
                for (int jj = 0; jj < 4; jj++) s[i][jj] *= sc;
        }

        // online softmax
        float alpha[4];
#pragma unroll
        for (int i = 0; i < 4; i++) {
            float rm = fmaxf(fmaxf(s[i][0], s[i][1]), fmaxf(s[i][2], s[i][3]));
#pragma unroll
            for (int off = 1; off < 16; off <<= 1)
                rm = fmaxf(rm, __shfl_xor_sync(0xffffffffu, rm, off, 16));
            float mnew = fmaxf(m[i], rm);
            alpha[i] = __expf(m[i] - mnew);
            m[i] = mnew;
            float rs = 0.f;
#pragma unroll
            for (int jj = 0; jj < 4; jj++) {
                float p = __expf(s[i][jj] - mnew);
                s[i][jj] = p;
                rs += p;
            }
#pragma unroll
            for (int off = 1; off < 16; off <<= 1)
                rs += __shfl_xor_sync(0xffffffffu, rs, off, 16);
            l[i] = l[i] * alpha[i] + rs;
            *reinterpret_cast<float4*>(&Ps[(r0 + i) * FS + c0]) =
                make_float4(s[i][0], s[i][1], s[i][2], s[i][3]);
        }
        __syncthreads();  // Ps visible to all

        // O = O*alpha + P V
#pragma unroll
        for (int i = 0; i < 4; i++)
#pragma unroll
            for (int jj = 0; jj < 4; jj++) o[i][jj] *= alpha[i];

        for (int c = 0; c < 64; c++) {
            float4 v4 = *reinterpret_cast<const float4*>(&Vs[c * FS + c0]);
#pragma unroll
            for (int i = 0; i < 4; i++) {
                float p = Ps[(r0 + i) * FS + c];
                o[i][0] += p * v4.x; o[i][1] += p * v4.y;
                o[i][2] += p * v4.z; o[i][3] += p * v4.w;
            }
        }
    }

    // epilogue: normalize + store
#pragma unroll
    for (int i = 0; i < 4; i++) {
        float invl = 1.f / l[i];
        float* dst = Og + (size_t)(qt * 64 + r0 + i) * C_DIM + h * HDIM + c0;
        *reinterpret_cast<float4*>(dst) =
            make_float4(o[i][0] * invl, o[i][1] * invl, o[i][2] * invl, o[i][3] * invl);
    }
}

// ---------------- launch -----------------------------------------------------
extern "C" void kernel_launch(void* const* d_in, const int* in_sizes, int n_in,
                              void* d_out, int out_size)
{
    const float* x      = (const float*)d_in[0];
    const float* wq     = (const float*)d_in[1];
    const float* wk     = (const float*)d_in[2];
    const float* wv     = (const float*)d_in[3];
    const float* wo     = (const float*)d_in[4];
    const float* norm_w = (const float*)d_in[5];
    float* out = (float*)d_out;

    float *normed, *q, *k, *v, *att;
    cudaGetSymbolAddress((void**)&normed, g_normed);
    cudaGetSymbolAddress((void**)&q,      g_q);
    cudaGetSymbolAddress((void**)&k,      g_k);
    cudaGetSymbolAddress((void**)&v,      g_v);
    cudaGetSymbolAddress((void**)&att,    g_att);

    // 1) RMSNorm
    rmsnorm_kernel<<<T_SEQ, 256>>>(x, norm_w, normed);

    // 2) Q/K/V projections on tensor cores (mma.sync tf32, 3-term split)
    cudaFuncSetAttribute(gemm_mma_kernel, cudaFuncAttributeMaxDynamicSharedMemorySize,
                         G_SMEM_TOTAL);
    dim3 gdim(C_DIM / G_BN, T_SEQ / G_BM);
    gemm_mma_kernel<<<gdim, 256, G_SMEM_TOTAL>>>(normed, wq, nullptr, q, T_SEQ, C_DIM, C_DIM);
    gemm_mma_kernel<<<gdim, 256, G_SMEM_TOTAL>>>(normed, wk, nullptr, k, T_SEQ, C_DIM, C_DIM);
    gemm_mma_kernel<<<gdim, 256, G_SMEM_TOTAL>>>(normed, wv, nullptr, v, T_SEQ, C_DIM, C_DIM);

    // 3) RoPE on q,k
    int nrope = T_SEQ * NHEADS * 32;
    rope_kernel<<<(nrope + 255) / 256, 256>>>(q, k);

    // 4) causal flash attention
    cudaFuncSetAttribute(flash_kernel, cudaFuncAttributeMaxDynamicSharedMemorySize,
                         FLASH_SMEM);
    dim3 fgrid(T_SEQ / 64, NHEADS);
    flash_kernel<<<fgrid, 256, FLASH_SMEM>>>(q, k, v, att);

    // 5) output projection + residual
    gemm_mma_kernel<<<gdim, 256, G_SMEM_TOTAL>>>(att, wo, x, out, T_SEQ, C_DIM, C_DIM);
}

// round 5
// speedup vs baseline: 2.1199x; 1.8518x over previous
#include <cuda_runtime.h>
#include <math.h>
#include <stdint.h>

#define T_SEQ   4096
#define C_DIM   1024
#define NHEADS  16
#define HDIM    64

// ---------------- scratch (static device globals; no allocation) -------------
__device__ float g_normed[T_SEQ * C_DIM];
__device__ float g_q[T_SEQ * C_DIM];
__device__ float g_k[T_SEQ * C_DIM];
__device__ float g_v[T_SEQ * C_DIM];
__device__ float g_att[T_SEQ * C_DIM];

// ================= tf32 helpers ==============================================
__device__ __forceinline__ void split_tf32(float a, float& hi, float& lo)
{
    uint32_t h;
    asm("cvt.rna.tf32.f32 %0, %1;" : "=r"(h) : "f"(a));
    hi = __uint_as_float(h);
    float r = a - hi;
    uint32_t l2;
    asm("cvt.rna.tf32.f32 %0, %1;" : "=r"(l2) : "f"(r));
    lo = __uint_as_float(l2);
}

__device__ __forceinline__ float to_tf32(float a)
{
    uint32_t u;
    asm("cvt.rna.tf32.f32 %0, %1;" : "=r"(u) : "f"(a));
    return __uint_as_float(u);
}

// m16n8k8 tf32 mma (sm_80+ baseline PTX, runs on tensor pipe)
__device__ __forceinline__ void mma_tf32(float d[4],
                                         float a0, float a1, float a2, float a3,
                                         float b0, float b1)
{
    asm volatile(
        "mma.sync.aligned.m16n8k8.row.col.f32.tf32.tf32.f32 "
        "{%0,%1,%2,%3}, {%4,%5,%6,%7}, {%8,%9}, {%0,%1,%2,%3};"
        : "+f"(d[0]), "+f"(d[1]), "+f"(d[2]), "+f"(d[3])
        : "r"(__float_as_uint(a0)), "r"(__float_as_uint(a1)),
          "r"(__float_as_uint(a2)), "r"(__float_as_uint(a3)),
          "r"(__float_as_uint(b0)), "r"(__float_as_uint(b1)));
}

// ================= HMMA tf32 GEMM: C[M,N] = A[M,K] @ B[N,K]^T (+Res) =========
#define G_BM 128
#define G_BN 128
#define G_BK 32
#define G_SK 36
#define G_PLANE (128 * G_SK)
#define G_BUF   (4 * G_PLANE)
#define G_SMEM_TOTAL (2 * G_BUF * 4)

__device__ __forceinline__ void ldg_tile(const float* __restrict__ G, int ldk,
                                         int k0, int tid, float4 r[4])
{
#pragma unroll
    for (int v = 0; v < 4; v++) {
        int i = tid + v * 256;
        int row = i >> 3;
        int c4 = i & 7;
        r[v] = *reinterpret_cast<const float4*>(G + (size_t)row * ldk + k0 + c4 * 4);
    }
}

__device__ __forceinline__ void sts_split(const float4 r[4], float* __restrict__ hi,
                                          float* __restrict__ lo, int tid)
{
#pragma unroll
    for (int v = 0; v < 4; v++) {
        int i = tid + v * 256;
        int row = i >> 3;
        int c4 = i & 7;
        int off = row * G_SK + c4 * 4;
        float4 h4, l4;
        split_tf32(r[v].x, h4.x, l4.x);
        split_tf32(r[v].y, h4.y, l4.y);
        split_tf32(r[v].z, h4.z, l4.z);
        split_tf32(r[v].w, h4.w, l4.w);
        *reinterpret_cast<float4*>(hi + off) = h4;
        *reinterpret_cast<float4*>(lo + off) = l4;
    }
}

__global__ __launch_bounds__(256, 1)
void gemm_mma_kernel(const float* __restrict__ A, const float* __restrict__ B,
                     const float* __restrict__ Res, float* __restrict__ Cm,
                     int M, int N, int K)
{
    extern __shared__ float sm[];
    int tid = threadIdx.x;
    int wid = tid >> 5;
    int lane = tid & 31;
    int gid = lane >> 2;
    int tig = lane & 3;
    int wm = wid & 1;
    int wn = wid >> 1;

    const float* Atile = A + (size_t)(blockIdx.y * G_BM) * K;
    const float* Btile = B + (size_t)(blockIdx.x * G_BN) * K;

    float acc[4][4][4];
#pragma unroll
    for (int mi = 0; mi < 4; mi++)
#pragma unroll
        for (int ni = 0; ni < 4; ni++)
#pragma unroll
            for (int e = 0; e < 4; e++) acc[mi][ni][e] = 0.f;

    const int NCHUNK = K / G_BK;

    float4 ra[4], rb[4];
    ldg_tile(Atile, K, 0, tid, ra);
    ldg_tile(Btile, K, 0, tid, rb);
    {
        float* base = sm;
        sts_split(ra, base + 0 * G_PLANE, base + 1 * G_PLANE, tid);
        sts_split(rb, base + 2 * G_PLANE, base + 3 * G_PLANE, tid);
    }
    __syncthreads();

    for (int kc = 0; kc < NCHUNK; kc++) {
        int cur = kc & 1;
        if (kc + 1 < NCHUNK) {
            ldg_tile(Atile, K, (kc + 1) * G_BK, tid, ra);
            ldg_tile(Btile, K, (kc + 1) * G_BK, tid, rb);
        }

        const float* Ahi = sm + cur * G_BUF;
        const float* Alo = Ahi + G_PLANE;
        const float* Bhi = Alo + G_PLANE;
        const float* Blo = Bhi + G_PLANE;

#pragma unroll
        for (int ks = 0; ks < 4; ks++) {
            int kk = ks * 8;
            float Ah[4][4], Al[4][4];
#pragma unroll
            for (int mi = 0; mi < 4; mi++) {
                int mrow = wm * 64 + mi * 16 + gid;
                int base = mrow * G_SK + kk + tig;
                Ah[mi][0] = Ahi[base];
                Ah[mi][1] = Ahi[base + 8 * G_SK];
                Ah[mi][2] = Ahi[base + 4];
                Ah[mi][3] = Ahi[base + 8 * G_SK + 4];
                Al[mi][0] = Alo[base];
                Al[mi][1] = Alo[base + 8 * G_SK];
                Al[mi][2] = Alo[base + 4];
                Al[mi][3] = Alo[base + 8 * G_SK + 4];
            }
            float Bh[4][2], Bl[4][2];
#pragma unroll
            for (int ni = 0; ni < 4; ni++) {
                int ncol = wn * 32 + ni * 8 + gid;
                int base = ncol * G_SK + kk + tig;
                Bh[ni][0] = Bhi[base];
                Bh[ni][1] = Bhi[base + 4];
                Bl[ni][0] = Blo[base];
                Bl[ni][1] = Blo[base + 4];
            }
#pragma unroll
            for (int mi = 0; mi < 4; mi++)
#pragma unroll
                for (int ni = 0; ni < 4; ni++) {
                    mma_tf32(acc[mi][ni], Ah[mi][0], Ah[mi][1], Ah[mi][2], Ah[mi][3],
                             Bh[ni][0], Bh[ni][1]);
                    mma_tf32(acc[mi][ni], Al[mi][0], Al[mi][1], Al[mi][2], Al[mi][3],
                             Bh[ni][0], Bh[ni][1]);
                    mma_tf32(acc[mi][ni], Ah[mi][0], Ah[mi][1], Ah[mi][2], Ah[mi][3],
                             Bl[ni][0], Bl[ni][1]);
                }
        }

        if (kc + 1 < NCHUNK) {
            float* base = sm + (1 - cur) * G_BUF;
            sts_split(ra, base + 0 * G_PLANE, base + 1 * G_PLANE, tid);
            sts_split(rb, base + 2 * G_PLANE, base + 3 * G_PLANE, tid);
        }
        __syncthreads();
    }

#pragma unroll
    for (int mi = 0; mi < 4; mi++) {
        int row0 = blockIdx.y * G_BM + wm * 64 + mi * 16 + gid;
#pragma unroll
        for (int ni = 0; ni < 4; ni++) {
            int col = blockIdx.x * G_BN + wn * 32 + ni * 8 + 2 * tig;
            float* d0 = Cm + (size_t)row0 * N + col;
            float* d1 = Cm + (size_t)(row0 + 8) * N + col;
            float2 v0 = make_float2(acc[mi][ni][0], acc[mi][ni][1]);
            float2 v1 = make_float2(acc[mi][ni][2], acc[mi][ni][3]);
            if (Res) {
                const float2 r0 = *reinterpret_cast<const float2*>(Res + (size_t)row0 * N + col);
                const float2 r1 = *reinterpret_cast<const float2*>(Res + (size_t)(row0 + 8) * N + col);
                v0.x += r0.x; v0.y += r0.y;
                v1.x += r1.x; v1.y += r1.y;
            }
            *reinterpret_cast<float2*>(d0) = v0;
            *reinterpret_cast<float2*>(d1) = v1;
        }
    }
}

// ---------------- RMSNorm ----------------------------------------------------
__global__ void rmsnorm_kernel(const float* __restrict__ x,
                               const float* __restrict__ w,
                               float* __restrict__ out)
{
    int row = blockIdx.x;
    const float4* xr = reinterpret_cast<const float4*>(x + (size_t)row * C_DIM);
    float ss = 0.f;
    for (int i = threadIdx.x; i < C_DIM / 4; i += blockDim.x) {
        float4 v = xr[i];
        ss += v.x * v.x + v.y * v.y + v.z * v.z + v.w * v.w;
    }
#pragma unroll
    for (int o = 16; o; o >>= 1) ss += __shfl_xor_sync(0xffffffffu, ss, o);

    __shared__ float red[8];
    __shared__ float s_inv;
    if ((threadIdx.x & 31) == 0) red[threadIdx.x >> 5] = ss;
    __syncthreads();
    if (threadIdx.x == 0) {
        float tot = 0.f;
        int nw = blockDim.x >> 5;
        for (int i = 0; i < nw; i++) tot += red[i];
        s_inv = rsqrtf(tot * (1.0f / C_DIM) + 1e-6f);
    }
    __syncthreads();
    float inv = s_inv;
    const float4* wr = reinterpret_cast<const float4*>(w);
    float4* outr = reinterpret_cast<float4*>(out + (size_t)row * C_DIM);
    for (int i = threadIdx.x; i < C_DIM / 4; i += blockDim.x) {
        float4 v = xr[i], ww = wr[i];
        v.x = v.x * inv * ww.x;
        v.y = v.y * inv * ww.y;
        v.z = v.z * inv * ww.z;
        v.w = v.w * inv * ww.w;
        outr[i] = v;
    }
}

// ---------------- RoPE (applied to q and k in place) -------------------------
__global__ void rope_kernel(float* __restrict__ q, float* __restrict__ k)
{
    int idx = blockIdx.x * blockDim.x + threadIdx.x;
    if (idx >= T_SEQ * NHEADS * 32) return;
    int i = idx & 31;
    int h = (idx >> 5) & (NHEADS - 1);
    int t = idx >> 9;
    float freq = powf(10000.0f, -(float)(2 * i) * (1.0f / 64.0f));
    float f = (float)t * freq;
    float s, c;
    sincosf(f, &s, &c);
    int base = t * C_DIM + h * HDIM;
    float q1 = q[base + i], q2 = q[base + i + 32];
    q[base + i]      = q1 * c - q2 * s;
    q[base + i + 32] = q2 * c + q1 * s;
    float k1 = k[base + i], k2 = k[base + i + 32];
    k[base + i]      = k1 * c - k2 * s;
    k[base + i + 32] = k2 * c + k1 * s;
}

// ---------------- Flash attention on tensor cores ----------------------------
// Br=Bc=64, 4 warps; warp w owns rows [w*16, w*16+16) of the q-tile (full 64 cols).
// S = QK^T via 2-term tf32 split (Qhi*Khi + Qlo*Khi); PV in plain tf32.
// Q pre-scaled by 1/sqrt(Dh)=0.125 (exact) before split.
#define FQ_STR 68   // smem float stride for Q/K/P planes (4*gid+tig banks)
#define FV_STR 72   // smem float stride for V plane (8*tig+gid banks)
#define F_SMEM_BYTES ((4 * 64 * FQ_STR + 64 * FV_STR) * 4)   // 88064

__global__ __launch_bounds__(128, 2)
void flash_mma_kernel(const float* __restrict__ Qg, const float* __restrict__ Kg,
                      const float* __restrict__ Vg, float* __restrict__ Og)
{
    extern __shared__ float sm[];
    float* Qhi = sm;
    float* Qlo = Qhi + 64 * FQ_STR;
    float* Kh  = Qlo + 64 * FQ_STR;
    float* Ps  = Kh  + 64 * FQ_STR;
    float* Vs  = Ps  + 64 * FQ_STR;

    int qt = (gridDim.x - 1) - blockIdx.x;   // heavy tiles first
    int h  = blockIdx.y;
    int tid = threadIdx.x;
    int wid = tid >> 5;
    int lane = tid & 31;
    int gid = lane >> 2;    // 0..7
    int tig = lane & 3;     // 0..3
    int wr0 = wid * 16;

    // ---- load Q tile (scale by 0.125, split to hi/lo) ----
#pragma unroll
    for (int v = 0; v < 8; v++) {
        int i = tid + v * 128;
        int row = i >> 4;
        int c4 = i & 15;
        float4 q4 = *reinterpret_cast<const float4*>(
            Qg + (size_t)(qt * 64 + row) * C_DIM + h * HDIM + c4 * 4);
        q4.x *= 0.125f; q4.y *= 0.125f; q4.z *= 0.125f; q4.w *= 0.125f;
        float4 h4, l4;
        split_tf32(q4.x, h4.x, l4.x);
        split_tf32(q4.y, h4.y, l4.y);
        split_tf32(q4.z, h4.z, l4.z);
        split_tf32(q4.w, h4.w, l4.w);
        *reinterpret_cast<float4*>(Qhi + row * FQ_STR + c4 * 4) = h4;
        *reinterpret_cast<float4*>(Qlo + row * FQ_STR + c4 * 4) = l4;
    }

    float oacc[8][4];
#pragma unroll
    for (int ni = 0; ni < 8; ni++)
#pragma unroll
        for (int e = 0; e < 4; e++) oacc[ni][e] = 0.f;
    float m0 = -INFINITY, m1 = -INFINITY;
    float l0 = 0.f, l1 = 0.f;

    for (int j = 0; j <= qt; j++) {
        __syncthreads();   // previous tile's smem reads complete (and Q on iter 0)

        // ---- load K (tf32-rounded) and V (tf32-rounded) tiles ----
#pragma unroll
        for (int v = 0; v < 8; v++) {
            int i = tid + v * 128;
            int row = i >> 4;
            int c4 = i & 15;
            float4 k4 = *reinterpret_cast<const float4*>(
                Kg + (size_t)(j * 64 + row) * C_DIM + h * HDIM + c4 * 4);
            k4.x = to_tf32(k4.x); k4.y = to_tf32(k4.y);
            k4.z = to_tf32(k4.z); k4.w = to_tf32(k4.w);
            *reinterpret_cast<float4*>(Kh + row * FQ_STR + c4 * 4) = k4;
            float4 v4 = *reinterpret_cast<const float4*>(
                Vg + (size_t)(j * 64 + row) * C_DIM + h * HDIM + c4 * 4);
            v4.x = to_tf32(v4.x); v4.y = to_tf32(v4.y);
            v4.z = to_tf32(v4.z); v4.w = to_tf32(v4.w);
            *reinterpret_cast<float4*>(Vs + row * FV_STR + c4 * 4) = v4;
        }
        __syncthreads();

        // ---- S = Q K^T (2-term split) ----
        float sacc[8][4];
#pragma unroll
        for (int ni = 0; ni < 8; ni++)
#pragma unroll
            for (int e = 0; e < 4; e++) sacc[ni][e] = 0.f;

#pragma unroll
        for (int kk = 0; kk < 8; kk++) {
            int kb = kk * 8;
            int abase = (wr0 + gid) * FQ_STR + kb + tig;
            float qh0 = Qhi[abase];
            float qh1 = Qhi[abase + 8 * FQ_STR];
            float qh2 = Qhi[abase + 4];
            float qh3 = Qhi[abase + 8 * FQ_STR + 4];
            float ql0 = Qlo[abase];
            float ql1 = Qlo[abase + 8 * FQ_STR];
            float ql2 = Qlo[abase + 4];
            float ql3 = Qlo[abase + 8 * FQ_STR + 4];
#pragma unroll
            for (int ni = 0; ni < 8; ni++) {
                int bbase = (ni * 8 + gid) * FQ_STR + kb + tig;
                float b0 = Kh[bbase];
                float b1 = Kh[bbase + 4];
                mma_tf32(sacc[ni], qh0, qh1, qh2, qh3, b0, b1);
                mma_tf32(sacc[ni], ql0, ql1, ql2, ql3, b0, b1);
            }
        }

        // ---- causal mask on diagonal tile ----
        if (j == qt) {
#pragma unroll
            for (int ni = 0; ni < 8; ni++) {
                int c0 = ni * 8 + 2 * tig;
                int rA = wr0 + gid, rB = wr0 + gid + 8;
                if (c0 > rA)     sacc[ni][0] = -INFINITY;
                if (c0 + 1 > rA) sacc[ni][1] = -INFINITY;
                if (c0 > rB)     sacc[ni][2] = -INFINITY;
                if (c0 + 1 > rB) sacc[ni][3] = -INFINITY;
            }
        }

        // ---- online softmax (rows gid and gid+8 of this warp's slab) ----
        float rm0 = -INFINITY, rm1 = -INFINITY;
#pragma unroll
        for (int ni = 0; ni < 8; ni++) {
            rm0 = fmaxf(rm0, fmaxf(sacc[ni][0], sacc[ni][1]));
            rm1 = fmaxf(rm1, fmaxf(sacc[ni][2], sacc[ni][3]));
        }
        rm0 = fmaxf(rm0, __shfl_xor_sync(0xffffffffu, rm0, 1));
        rm0 = fmaxf(rm0, __shfl_xor_sync(0xffffffffu, rm0, 2));
        rm1 = fmaxf(rm1, __shfl_xor_sync(0xffffffffu, rm1, 1));
        rm1 = fmaxf(rm1, __shfl_xor_sync(0xffffffffu, rm1, 2));

        float mn0 = fmaxf(m0, rm0);
        float mn1 = fmaxf(m1, rm1);
        float alpha0 = __expf(m0 - mn0);
        float alpha1 = __expf(m1 - mn1);
        m0 = mn0; m1 = mn1;

        float rs0 = 0.f, rs1 = 0.f;
#pragma unroll
        for (int ni = 0; ni < 8; ni++) {
            float p0 = __expf(sacc[ni][0] - mn0);
            float p1 = __expf(sacc[ni][1] - mn0);
            float p2 = __expf(sacc[ni][2] - mn1);
            float p3 = __expf(sacc[ni][3] - mn1);
            rs0 += p0 + p1;
            rs1 += p2 + p3;
            int c0 = ni * 8 + 2 * tig;
            *reinterpret_cast<float2*>(Ps + (wr0 + gid) * FQ_STR + c0) =
                make_float2(to_tf32(p0), to_tf32(p1));
            *reinterpret_cast<float2*>(Ps + (wr0 + gid + 8) * FQ_STR + c0) =
                make_float2(to_tf32(p2), to_tf32(p3));
        }
        rs0 += __shfl_xor_sync(0xffffffffu, rs0, 1);
        rs0 += __shfl_xor_sync(0xffffffffu, rs0, 2);
        rs1 += __shfl_xor_sync(0xffffffffu, rs1, 1);
        rs1 += __shfl_xor_sync(0xffffffffu, rs1, 2);
        l0 = l0 * alpha0 + rs0;
        l1 = l1 * alpha1 + rs1;

#pragma unroll
        for (int ni = 0; ni < 8; ni++) {
            oacc[ni][0] *= alpha0; oacc[ni][1] *= alpha0;
            oacc[ni][2] *= alpha1; oacc[ni][3] *= alpha1;
        }
        __syncwarp();   // Ps rows of this warp visible to the whole warp

        // ---- O += P V ----
#pragma unroll
        for (int kk = 0; kk < 8; kk++) {
            int kb = kk * 8;
            int abase = (wr0 + gid) * FQ_STR + kb + tig;
            float a0 = Ps[abase];
            float a1 = Ps[abase + 8 * FQ_STR];
            float a2 = Ps[abase + 4];
            float a3 = Ps[abase + 8 * FQ_STR + 4];
#pragma unroll
            for (int ni = 0; ni < 8; ni++) {
                float b0 = Vs[(kb + tig) * FV_STR + ni * 8 + gid];
                float b1 = Vs[(kb + tig + 4) * FV_STR + ni * 8 + gid];
                mma_tf32(oacc[ni], a0, a1, a2, a3, b0, b1);
            }
        }
    }

    // ---- epilogue: normalize and store ----
    float invl0 = 1.f / l0;
    float invl1 = 1.f / l1;
    int row0 = qt * 64 + wr0 + gid;
    int row1 = row0 + 8;
#pragma unroll
    for (int ni = 0; ni < 8; ni++) {
        int col = h * HDIM + ni * 8 + 2 * tig;
        *reinterpret_cast<float2*>(Og + (size_t)row0 * C_DIM + col) =
            make_float2(oacc[ni][0] * invl0, oacc[ni][1] * invl0);
        *reinterpret_cast<float2*>(Og + (size_t)row1 * C_DIM + col) =
            make_float2(oacc[ni][2] * invl1, oacc[ni][3] * invl1);
    }
}

// ---------------- launch -----------------------------------------------------
extern "C" void kernel_launch(void* const* d_in, const int* in_sizes, int n_in,
                              void* d_out, int out_size)
{
    const float* x      = (const float*)d_in[0];
    const float* wq     = (const float*)d_in[1];
    const float* wk     = (const float*)d_in[2];
    const float* wv     = (const float*)d_in[3];
    const float* wo     = (const float*)d_in[4];
    const float* norm_w = (const float*)d_in[5];
    float* out = (float*)d_out;

    float *normed, *q, *k, *v, *att;
    cudaGetSymbolAddress((void**)&normed, g_normed);
    cudaGetSymbolAddress((void**)&q,      g_q);
    cudaGetSymbolAddress((void**)&k,      g_k);
    cudaGetSymbolAddress((void**)&v,      g_v);
    cudaGetSymbolAddress((void**)&att,    g_att);

    // 1) RMSNorm
    rmsnorm_kernel<<<T_SEQ, 256>>>(x, norm_w, normed);

    // 2) Q/K/V projections on tensor cores (mma.sync tf32, 3-term split)
    cudaFuncSetAttribute(gemm_mma_kernel, cudaFuncAttributeMaxDynamicSharedMemorySize,
                         G_SMEM_TOTAL);
    dim3 gdim(C_DIM / G_BN, T_SEQ / G_BM);
    gemm_mma_kernel<<<gdim, 256, G_SMEM_TOTAL>>>(normed, wq, nullptr, q, T_SEQ, C_DIM, C_DIM);
    gemm_mma_kernel<<<gdim, 256, G_SMEM_TOTAL>>>(normed, wk, nullptr, k, T_SEQ, C_DIM, C_DIM);
    gemm_mma_kernel<<<gdim, 256, G_SMEM_TOTAL>>>(normed, wv, nullptr, v, T_SEQ, C_DIM, C_DIM);

    // 3) RoPE on q,k
    int nrope = T_SEQ * NHEADS * 32;
    rope_kernel<<<(nrope + 255) / 256, 256>>>(q, k);

    // 4) causal flash attention on tensor cores
    cudaFuncSetAttribute(flash_mma_kernel, cudaFuncAttributeMaxDynamicSharedMemorySize,
                         F_SMEM_BYTES);
    dim3 fgrid(T_SEQ / 64, NHEADS);
    flash_mma_kernel<<<fgrid, 128, F_SMEM_BYTES>>>(q, k, v, att);

    // 5) output projection + residual
    gemm_mma_kernel<<<gdim, 256, G_SMEM_TOTAL>>>(att, wo, x, out, T_SEQ, C_DIM, C_DIM);
}

// round 7
// speedup vs baseline: 2.4685x; 1.1644x over previous
#include <cuda_runtime.h>
#include <math.h>
#include <stdint.h>

#define T_SEQ   4096
#define C_DIM   1024
#define NHEADS  16
#define HDIM    64

// ---------------- scratch (static device globals; no allocation) -------------
__device__ float g_normed[T_SEQ * C_DIM];
__device__ float g_q[T_SEQ * C_DIM];
__device__ float g_k[T_SEQ * C_DIM];
__device__ float g_v[T_SEQ * C_DIM];
__device__ float g_att[T_SEQ * C_DIM];

// ================= tf32 helpers ==============================================
__device__ __forceinline__ void split_tf32(float a, float& hi, float& lo)
{
    uint32_t h;
    asm("cvt.rna.tf32.f32 %0, %1;" : "=r"(h) : "f"(a));
    hi = __uint_as_float(h);
    float r = a - hi;
    uint32_t l2;
    asm("cvt.rna.tf32.f32 %0, %1;" : "=r"(l2) : "f"(r));
    lo = __uint_as_float(l2);
}

__device__ __forceinline__ float to_tf32(float a)
{
    uint32_t u;
    asm("cvt.rna.tf32.f32 %0, %1;" : "=r"(u) : "f"(a));
    return __uint_as_float(u);
}

// m16n8k8 tf32 mma (sm_80+ baseline PTX, runs on tensor pipe)
__device__ __forceinline__ void mma_tf32(float d[4],
                                         float a0, float a1, float a2, float a3,
                                         float b0, float b1)
{
    asm volatile(
        "mma.sync.aligned.m16n8k8.row.col.f32.tf32.tf32.f32 "
        "{%0,%1,%2,%3}, {%4,%5,%6,%7}, {%8,%9}, {%0,%1,%2,%3};"
        : "+f"(d[0]), "+f"(d[1]), "+f"(d[2]), "+f"(d[3])
        : "r"(__float_as_uint(a0)), "r"(__float_as_uint(a1)),
          "r"(__float_as_uint(a2)), "r"(__float_as_uint(a3)),
          "r"(__float_as_uint(b0)), "r"(__float_as_uint(b1)));
}

// ================= HMMA tf32 GEMM: C[M,N] = A[M,K] @ B[N,K]^T (+Res) =========
// 2-term split: Ahi*Bhi + Alo*Bhi (B rounded to tf32). 3 smem planes.
#define G_BM 128
#define G_BN 128
#define G_BK 32
#define G_SK 36
#define G_PLANE (128 * G_SK)
#define G_BUF   (3 * G_PLANE)            // Ahi, Alo, Bhi
#define G_SMEM_TOTAL (2 * G_BUF * 4)     // 110592 bytes

__device__ __forceinline__ void ldg_tile(const float* __restrict__ G, int ldk,
                                         int k0, int tid, float4 r[4])
{
#pragma unroll
    for (int v = 0; v < 4; v++) {
        int i = tid + v * 256;
        int row = i >> 3;
        int c4 = i & 7;
        r[v] = *reinterpret_cast<const float4*>(G + (size_t)row * ldk + k0 + c4 * 4);
    }
}

__device__ __forceinline__ void sts_split(const float4 r[4], float* __restrict__ hi,
                                          float* __restrict__ lo, int tid)
{
#pragma unroll
    for (int v = 0; v < 4; v++) {
        int i = tid + v * 256;
        int row = i >> 3;
        int c4 = i & 7;
        int off = row * G_SK + c4 * 4;
        float4 h4, l4;
        split_tf32(r[v].x, h4.x, l4.x);
        split_tf32(r[v].y, h4.y, l4.y);
        split_tf32(r[v].z, h4.z, l4.z);
        split_tf32(r[v].w, h4.w, l4.w);
        *reinterpret_cast<float4*>(hi + off) = h4;
        *reinterpret_cast<float4*>(lo + off) = l4;
    }
}

__device__ __forceinline__ void sts_round(const float4 r[4], float* __restrict__ hi,
                                          int tid)
{
#pragma unroll
    for (int v = 0; v < 4; v++) {
        int i = tid + v * 256;
        int row = i >> 3;
        int c4 = i & 7;
        int off = row * G_SK + c4 * 4;
        float4 h4;
        h4.x = to_tf32(r[v].x);
        h4.y = to_tf32(r[v].y);
        h4.z = to_tf32(r[v].z);
        h4.w = to_tf32(r[v].w);
        *reinterpret_cast<float4*>(hi + off) = h4;
    }
}

__global__ __launch_bounds__(256, 1)
void gemm_mma_kernel(const float* __restrict__ A, const float* __restrict__ B,
                     const float* __restrict__ Res, float* __restrict__ Cm,
                     int M, int N, int K)
{
    extern __shared__ float sm[];
    int tid = threadIdx.x;
    int wid = tid >> 5;
    int lane = tid & 31;
    int gid = lane >> 2;
    int tig = lane & 3;
    int wm = wid & 1;
    int wn = wid >> 1;

    const float* Atile = A + (size_t)(blockIdx.y * G_BM) * K;
    const float* Btile = B + (size_t)(blockIdx.x * G_BN) * K;

    float acc[4][4][4];
#pragma unroll
    for (int mi = 0; mi < 4; mi++)
#pragma unroll
        for (int ni = 0; ni < 4; ni++)
#pragma unroll
            for (int e = 0; e < 4; e++) acc[mi][ni][e] = 0.f;

    const int NCHUNK = K / G_BK;

    float4 ra[4], rb[4];
    ldg_tile(Atile, K, 0, tid, ra);
    ldg_tile(Btile, K, 0, tid, rb);
    {
        float* base = sm;
        sts_split(ra, base + 0 * G_PLANE, base + 1 * G_PLANE, tid);
        sts_round(rb, base + 2 * G_PLANE, tid);
    }
    __syncthreads();

    for (int kc = 0; kc < NCHUNK; kc++) {
        int cur = kc & 1;
        if (kc + 1 < NCHUNK) {
            ldg_tile(Atile, K, (kc + 1) * G_BK, tid, ra);
            ldg_tile(Btile, K, (kc + 1) * G_BK, tid, rb);
        }

        const float* Ahi = sm + cur * G_BUF;
        const float* Alo = Ahi + G_PLANE;
        const float* Bhi = Alo + G_PLANE;

#pragma unroll
        for (int ks = 0; ks < 4; ks++) {
            int kk = ks * 8;
            float Ah[4][4], Al[4][4];
#pragma unroll
            for (int mi = 0; mi < 4; mi++) {
                int mrow = wm * 64 + mi * 16 + gid;
                int base = mrow * G_SK + kk + tig;
                Ah[mi][0] = Ahi[base];
                Ah[mi][1] = Ahi[base + 8 * G_SK];
                Ah[mi][2] = Ahi[base + 4];
                Ah[mi][3] = Ahi[base + 8 * G_SK + 4];
                Al[mi][0] = Alo[base];
                Al[mi][1] = Alo[base + 8 * G_SK];
                Al[mi][2] = Alo[base + 4];
                Al[mi][3] = Alo[base + 8 * G_SK + 4];
            }
            float Bh[4][2];
#pragma unroll
            for (int ni = 0; ni < 4; ni++) {
                int ncol = wn * 32 + ni * 8 + gid;
                int base = ncol * G_SK + kk + tig;
                Bh[ni][0] = Bhi[base];
                Bh[ni][1] = Bhi[base + 4];
            }
#pragma unroll
            for (int mi = 0; mi < 4; mi++)
#pragma unroll
                for (int ni = 0; ni < 4; ni++) {
                    mma_tf32(acc[mi][ni], Ah[mi][0], Ah[mi][1], Ah[mi][2], Ah[mi][3],
                             Bh[ni][0], Bh[ni][1]);
                    mma_tf32(acc[mi][ni], Al[mi][0], Al[mi][1], Al[mi][2], Al[mi][3],
                             Bh[ni][0], Bh[ni][1]);
                }
        }

        if (kc + 1 < NCHUNK) {
            float* base = sm + (1 - cur) * G_BUF;
            sts_split(ra, base + 0 * G_PLANE, base + 1 * G_PLANE, tid);
            sts_round(rb, base + 2 * G_PLANE, tid);
        }
        __syncthreads();
    }

#pragma unroll
    for (int mi = 0; mi < 4; mi++) {
        int row0 = blockIdx.y * G_BM + wm * 64 + mi * 16 + gid;
#pragma unroll
        for (int ni = 0; ni < 4; ni++) {
            int col = blockIdx.x * G_BN + wn * 32 + ni * 8 + 2 * tig;
            float* d0 = Cm + (size_t)row0 * N + col;
            float* d1 = Cm + (size_t)(row0 + 8) * N + col;
            float2 v0 = make_float2(acc[mi][ni][0], acc[mi][ni][1]);
            float2 v1 = make_float2(acc[mi][ni][2], acc[mi][ni][3]);
            if (Res) {
                const float2 r0 = *reinterpret_cast<const float2*>(Res + (size_t)row0 * N + col);
                const float2 r1 = *reinterpret_cast<const float2*>(Res + (size_t)(row0 + 8) * N + col);
                v0.x += r0.x; v0.y += r0.y;
                v1.x += r1.x; v1.y += r1.y;
            }
            *reinterpret_cast<float2*>(d0) = v0;
            *reinterpret_cast<float2*>(d1) = v1;
        }
    }
}

// ---------------- RMSNorm ----------------------------------------------------
__global__ void rmsnorm_kernel(const float* __restrict__ x,
                               const float* __restrict__ w,
                               float* __restrict__ out)
{
    int row = blockIdx.x;
    const float4* xr = reinterpret_cast<const float4*>(x + (size_t)row * C_DIM);
    float ss = 0.f;
    for (int i = threadIdx.x; i < C_DIM / 4; i += blockDim.x) {
        float4 v = xr[i];
        ss += v.x * v.x + v.y * v.y + v.z * v.z + v.w * v.w;
    }
#pragma unroll
    for (int o = 16; o; o >>= 1) ss += __shfl_xor_sync(0xffffffffu, ss, o);

    __shared__ float red[8];
    __shared__ float s_inv;
    if ((threadIdx.x & 31) == 0) red[threadIdx.x >> 5] = ss;
    __syncthreads();
    if (threadIdx.x == 0) {
        float tot = 0.f;
        int nw = blockDim.x >> 5;
        for (int i = 0; i < nw; i++) tot += red[i];
        s_inv = rsqrtf(tot * (1.0f / C_DIM) + 1e-6f);
    }
    __syncthreads();
    float inv = s_inv;
    const float4* wr = reinterpret_cast<const float4*>(w);
    float4* outr = reinterpret_cast<float4*>(out + (size_t)row * C_DIM);
    for (int i = threadIdx.x; i < C_DIM / 4; i += blockDim.x) {
        float4 v = xr[i], ww = wr[i];
        v.x = v.x * inv * ww.x;
        v.y = v.y * inv * ww.y;
        v.z = v.z * inv * ww.z;
        v.w = v.w * inv * ww.w;
        outr[i] = v;
    }
}

// ---------------- RoPE (applied to q and k in place) -------------------------
__global__ void rope_kernel(float* __restrict__ q, float* __restrict__ k)
{
    int idx = blockIdx.x * blockDim.x + threadIdx.x;
    if (idx >= T_SEQ * NHEADS * 32) return;
    int i = idx & 31;
    int h = (idx >> 5) & (NHEADS - 1);
    int t = idx >> 9;
    float freq = powf(10000.0f, -(float)(2 * i) * (1.0f / 64.0f));
    float f = (float)t * freq;
    float s, c;
    sincosf(f, &s, &c);
    int base = t * C_DIM + h * HDIM;
    float q1 = q[base + i], q2 = q[base + i + 32];
    q[base + i]      = q1 * c - q2 * s;
    q[base + i + 32] = q2 * c + q1 * s;
    float k1 = k[base + i], k2 = k[base + i + 32];
    k[base + i]      = k1 * c - k2 * s;
    k[base + i + 32] = k2 * c + k1 * s;
}

// ---------------- Flash attention on tensor cores ----------------------------
#define FQ_STR 68
#define FV_STR 72
#define F_SMEM_BYTES ((4 * 64 * FQ_STR + 64 * FV_STR) * 4)

__global__ __launch_bounds__(128, 2)
void flash_mma_kernel(const float* __restrict__ Qg, const float* __restrict__ Kg,
                      const float* __restrict__ Vg, float* __restrict__ Og)
{
    extern __shared__ float sm[];
    float* Qhi = sm;
    float* Qlo = Qhi + 64 * FQ_STR;
    float* Kh  = Qlo + 64 * FQ_STR;
    float* Ps  = Kh  + 64 * FQ_STR;
    float* Vs  = Ps  + 64 * FQ_STR;

    int qt = (gridDim.x - 1) - blockIdx.x;
    int h  = blockIdx.y;
    int tid = threadIdx.x;
    int wid = tid >> 5;
    int lane = tid & 31;
    int gid = lane >> 2;
    int tig = lane & 3;
    int wr0 = wid * 16;

#pragma unroll
    for (int v = 0; v < 8; v++) {
        int i = tid + v * 128;
        int row = i >> 4;
        int c4 = i & 15;
        float4 q4 = *reinterpret_cast<const float4*>(
            Qg + (size_t)(qt * 64 + row) * C_DIM + h * HDIM + c4 * 4);
        q4.x *= 0.125f; q4.y *= 0.125f; q4.z *= 0.125f; q4.w *= 0.125f;
        float4 h4, l4;
        split_tf32(q4.x, h4.x, l4.x);
        split_tf32(q4.y, h4.y, l4.y);
        split_tf32(q4.z, h4.z, l4.z);
        split_tf32(q4.w, h4.w, l4.w);
        *reinterpret_cast<float4*>(Qhi + row * FQ_STR + c4 * 4) = h4;
        *reinterpret_cast<float4*>(Qlo + row * FQ_STR + c4 * 4) = l4;
    }

    float oacc[8][4];
#pragma unroll
    for (int ni = 0; ni < 8; ni++)
#pragma unroll
        for (int e = 0; e < 4; e++) oacc[ni][e] = 0.f;
    float m0 = -INFINITY, m1 = -INFINITY;
    float l0 = 0.f, l1 = 0.f;

    for (int j = 0; j <= qt; j++) {
        __syncthreads();

#pragma unroll
        for (int v = 0; v < 8; v++) {
            int i = tid + v * 128;
            int row = i >> 4;
            int c4 = i & 15;
            float4 k4 = *reinterpret_cast<const float4*>(
                Kg + (size_t)(j * 64 + row) * C_DIM + h * HDIM + c4 * 4);
            k4.x = to_tf32(k4.x); k4.y = to_tf32(k4.y);
            k4.z = to_tf32(k4.z); k4.w = to_tf32(k4.w);
            *reinterpret_cast<float4*>(Kh + row * FQ_STR + c4 * 4) = k4;
            float4 v4 = *reinterpret_cast<const float4*>(
                Vg + (size_t)(j * 64 + row) * C_DIM + h * HDIM + c4 * 4);
            v4.x = to_tf32(v4.x); v4.y = to_tf32(v4.y);
            v4.z = to_tf32(v4.z); v4.w = to_tf32(v4.w);
            *reinterpret_cast<float4*>(Vs + row * FV_STR + c4 * 4) = v4;
        }
        __syncthreads();

        float sacc[8][4];
#pragma unroll
        for (int ni = 0; ni < 8; ni++)
#pragma unroll
            for (int e = 0; e < 4; e++) sacc[ni][e] = 0.f;

#pragma unroll
        for (int kk = 0; kk < 8; kk++) {
            int kb = kk * 8;
            int abase = (wr0 + gid) * FQ_STR + kb + tig;
            float qh0 = Qhi[abase];
            float qh1 = Qhi[abase + 8 * FQ_STR];
            float qh2 = Qhi[abase + 4];
            float qh3 = Qhi[abase + 8 * FQ_STR + 4];
            float ql0 = Qlo[abase];
            float ql1 = Qlo[abase + 8 * FQ_STR];
            float ql2 = Qlo[abase + 4];
            float ql3 = Qlo[abase + 8 * FQ_STR + 4];
#pragma unroll
            for (int ni = 0; ni < 8; ni++) {
                int bbase = (ni * 8 + gid) * FQ_STR + kb + tig;
                float b0 = Kh[bbase];
                float b1 = Kh[bbase + 4];
                mma_tf32(sacc[ni], qh0, qh1, qh2, qh3, b0, b1);
                mma_tf32(sacc[ni], ql0, ql1, ql2, ql3, b0, b1);
            }
        }

        if (j == qt) {
#pragma unroll
            for (int ni = 0; ni < 8; ni++) {
                int c0 = ni * 8 + 2 * tig;
                int rA = wr0 + gid, rB = wr0 + gid + 8;
                if (c0 > rA)     sacc[ni][0] = -INFINITY;
                if (c0 + 1 > rA) sacc[ni][1] = -INFINITY;
                if (c0 > rB)     sacc[ni][2] = -INFINITY;
                if (c0 + 1 > rB) sacc[ni][3] = -INFINITY;
            }
        }

        float rm0 = -INFINITY, rm1 = -INFINITY;
#pragma unroll
        for (int ni = 0; ni < 8; ni++) {
            rm0 = fmaxf(rm0, fmaxf(sacc[ni][0], sacc[ni][1]));
            rm1 = fmaxf(rm1, fmaxf(sacc[ni][2], sacc[ni][3]));
        }
        rm0 = fmaxf(rm0, __shfl_xor_sync(0xffffffffu, rm0, 1));
        rm0 = fmaxf(rm0, __shfl_xor_sync(0xffffffffu, rm0, 2));
        rm1 = fmaxf(rm1, __shfl_xor_sync(0xffffffffu, rm1, 1));
        rm1 = fmaxf(rm1, __shfl_xor_sync(0xffffffffu, rm1, 2));

        float mn0 = fmaxf(m0, rm0);
        float mn1 = fmaxf(m1, rm1);
        float alpha0 = __expf(m0 - mn0);
        float alpha1 = __expf(m1 - mn1);
        m0 = mn0; m1 = mn1;

        float rs0 = 0.f, rs1 = 0.f;
#pragma unroll
        for (int ni = 0; ni < 8; ni++) {
            float p0 = __expf(sacc[ni][0] - mn0);
            float p1 = __expf(sacc[ni][1] - mn0);
            float p2 = __expf(sacc[ni][2] - mn1);
            float p3 = __expf(sacc[ni][3] - mn1);
            rs0 += p0 + p1;
            rs1 += p2 + p3;
            int c0 = ni * 8 + 2 * tig;
            *reinterpret_cast<float2*>(Ps + (wr0 + gid) * FQ_STR + c0) =
                make_float2(to_tf32(p0), to_tf32(p1));
            *reinterpret_cast<float2*>(Ps + (wr0 + gid + 8) * FQ_STR + c0) =
                make_float2(to_tf32(p2), to_tf32(p3));
        }
        rs0 += __shfl_xor_sync(0xffffffffu, rs0, 1);
        rs0 += __shfl_xor_sync(0xffffffffu, rs0, 2);
        rs1 += __shfl_xor_sync(0xffffffffu, rs1, 1);
        rs1 += __shfl_xor_sync(0xffffffffu, rs1, 2);
        l0 = l0 * alpha0 + rs0;
        l1 = l1 * alpha1 + rs1;

#pragma unroll
        for (int ni = 0; ni < 8; ni++) {
            oacc[ni][0] *= alpha0; oacc[ni][1] *= alpha0;
            oacc[ni][2] *= alpha1; oacc[ni][3] *= alpha1;
        }
        __syncwarp();

#pragma unroll
        for (int kk = 0; kk < 8; kk++) {
            int kb = kk * 8;
            int abase = (wr0 + gid) * FQ_STR + kb + tig;
            float a0 = Ps[abase];
            float a1 = Ps[abase + 8 * FQ_STR];
            float a2 = Ps[abase + 4];
            float a3 = Ps[abase + 8 * FQ_STR + 4];
#pragma unroll
            for (int ni = 0; ni < 8; ni++) {
                float b0 = Vs[(kb + tig) * FV_STR + ni * 8 + gid];
                float b1 = Vs[(kb + tig + 4) * FV_STR + ni * 8 + gid];
                mma_tf32(oacc[ni], a0, a1, a2, a3, b0, b1);
            }
        }
    }

    float invl0 = 1.f / l0;
    float invl1 = 1.f / l1;
    int row0 = qt * 64 + wr0 + gid;
    int row1 = row0 + 8;
#pragma unroll
    for (int ni = 0; ni < 8; ni++) {
        int col = h * HDIM + ni * 8 + 2 * tig;
        *reinterpret_cast<float2*>(Og + (size_t)row0 * C_DIM + col) =
            make_float2(oacc[ni][0] * invl0, oacc[ni][1] * invl0);
        *reinterpret_cast<float2*>(Og + (size_t)row1 * C_DIM + col) =
            make_float2(oacc[ni][2] * invl1, oacc[ni][3] * invl1);
    }
}

// ---------------- launch -----------------------------------------------------
extern "C" void kernel_launch(void* const* d_in, const int* in_sizes, int n_in,
                              void* d_out, int out_size)
{
    const float* x      = (const float*)d_in[0];
    const float* wq     = (const float*)d_in[1];
    const float* wk     = (const float*)d_in[2];
    const float* wv     = (const float*)d_in[3];
    const float* wo     = (const float*)d_in[4];
    const float* norm_w = (const float*)d_in[5];
    float* out = (float*)d_out;

    float *normed, *q, *k, *v, *att;
    cudaGetSymbolAddress((void**)&normed, g_normed);
    cudaGetSymbolAddress((void**)&q,      g_q);
    cudaGetSymbolAddress((void**)&k,      g_k);
    cudaGetSymbolAddress((void**)&v,      g_v);
    cudaGetSymbolAddress((void**)&att,    g_att);

    // 1) RMSNorm
    rmsnorm_kernel<<<T_SEQ, 256>>>(x, norm_w, normed);

    // 2) Q/K/V projections (mma.sync tf32, 2-term split)
    cudaFuncSetAttribute(gemm_mma_kernel, cudaFuncAttributeMaxDynamicSharedMemorySize,
                         G_SMEM_TOTAL);
    dim3 gdim(C_DIM / G_BN, T_SEQ / G_BM);
    gemm_mma_kernel<<<gdim, 256, G_SMEM_TOTAL>>>(normed, wq, nullptr, q, T_SEQ, C_DIM, C_DIM);
    gemm_mma_kernel<<<gdim, 256, G_SMEM_TOTAL>>>(normed, wk, nullptr, k, T_SEQ, C_DIM, C_DIM);
    gemm_mma_kernel<<<gdim, 256, G_SMEM_TOTAL>>>(normed, wv, nullptr, v, T_SEQ, C_DIM, C_DIM);

    // 3) RoPE on q,k
    int nrope = T_SEQ * NHEADS * 32;
    rope_kernel<<<(nrope + 255) / 256, 256>>>(q, k);

    // 4) causal flash attention on tensor cores
    cudaFuncSetAttribute(flash_mma_kernel, cudaFuncAttributeMaxDynamicSharedMemorySize,
                         F_SMEM_BYTES);
    dim3 fgrid(T_SEQ / 64, NHEADS);
    flash_mma_kernel<<<fgrid, 128, F_SMEM_BYTES>>>(q, k, v, att);

    // 5) output projection + residual
    gemm_mma_kernel<<<gdim, 256, G_SMEM_TOTAL>>>(att, wo, x, out, T_SEQ, C_DIM, C_DIM);
}